// round 5
// baseline (speedup 1.0000x reference)
#include <cuda_runtime.h>
#include <cuda_bf16.h>

// ---------------------------------------------------------------------------
// Model_70222715289880: bilinear score -> top-k(10/64) -> gather of 10 tensors
// B=8, K=64, TOPK=10, N_R=4, L_R=128, H=512, D=128, D2=640.
//
// R5: smem-staged, double-buffered tile pipeline for both GEMV phases.
// The per-warp outstanding-LDG cap (~55) made register prefetch serialize
// (R4 q_kernel: issue 6.3%). Cooperative float4 LDG->STS tiles sidestep the
// cap; fmaf chains read smem. FP summation order is BIT-IDENTICAL to the
// passing R2-R4 kernels (top-k ties at tanh plateaus depend on it).
// ---------------------------------------------------------------------------

#define Bq   8
#define Kk   64
#define TOPK 10
#define D2   640

#define OFF_SCORES   0
#define OFF_RATINGS  21238160
#define OFF_IDX      21248480

// vec4 (float4) offsets of gathered segments in dst
#define V4_SR    20u
#define V4_HR    40980u
#define V4_RA    5283860u
#define V4_RO    5294100u
#define V4_MASK  5304340u
#define V4_RB    5304420u
#define V4_RM    5306980u
#define V4_RE    5309560u

// gather-index range boundaries, in vec4 units
#define G_SR_END   40960u
#define G_HR_END   5283840u
#define G_RA_END   5294080u
#define G_RO_END   5304320u
#define G_MK_END   5304400u
#define G_RB_END   5306960u
#define G_RM_END   5309520u
#define G_RE_END   5312080u
#define G_TOTAL    5312080u

__device__ int   g_topk_idx[Bq * TOPK];
__device__ float g_q[Bq * D2];

// ---------------------------------------------------------------------------
// XLA's tanh (Eigen generic_fast_tanh_float as emitted by elemental_ir_emitter)
// ---------------------------------------------------------------------------
__device__ __forceinline__ float xla_tanhf(float x)
{
    const float kClamp = 7.90531110763549805f;
    float xc = fmaxf(-kClamp, fminf(x, kClamp));
    float x2 = xc * xc;

    float p = fmaf(x2, -2.76076847742355e-16f, 2.00018790482477e-13f);
    p = fmaf(x2, p, -8.60467152213735e-11f);
    p = fmaf(x2, p,  5.12229709037114e-08f);
    p = fmaf(x2, p,  1.48572235717979e-05f);
    p = fmaf(x2, p,  6.37261928875436e-04f);
    p = fmaf(x2, p,  4.89352455891786e-03f);
    p = xc * p;

    float q = fmaf(x2, 1.19825839466702e-06f, 1.18534705686654e-04f);
    q = fmaf(x2, q, 2.26843463243900e-03f);
    q = fmaf(x2, q, 4.89352518554385e-03f);

    float r = p / q;
    return (fabsf(x) < 0.0004f) ? x : r;
}

// total-order key on float (ascending)
__device__ __forceinline__ unsigned ord_f32(float f)
{
    int i = __float_as_int(f);
    return (i < 0) ? ~(unsigned)i : ((unsigned)i | 0x80000000u);
}

// ---------------------------------------------------------------------------
// Kernel Q: q[b][e] = sum_d a_s_q[b][d] * W[d][e]  (serial-d chain per e).
// Grid (8, 5) x 256 threads. Tiles of 32 d x 128 e staged in smem, double
// buffered; threads 0..127 run the chains, all 256 load.
// ---------------------------------------------------------------------------
#define QT 32           // d-rows per tile
#define QTILES 20       // 640 / 32

__global__ __launch_bounds__(256) void q_kernel(
    const float* __restrict__ a_s_q,
    const float* __restrict__ W)
{
    __shared__ float aq[D2];
    __shared__ float wt[2][QT * 128];

    const int b   = blockIdx.x;
    const int e0  = blockIdx.y * 128;
    const int tid = threadIdx.x;

    for (int i = tid; i < D2; i += 256) aq[i] = a_s_q[b * D2 + i];

    // tile t covers d in [32t, 32t+32), e in [e0, e0+128)
    const float* wbase = W + e0;
    {   // preload tile 0: 1024 float4, 4 per thread
        #pragma unroll
        for (int r = 0; r < 4; ++r) {
            const int j  = tid + 256 * r;
            const int dd = j >> 5;
            const int cc = j & 31;
            float4 v = *(const float4*)(wbase + dd * D2 + cc * 4);
            *(float4*)(&wt[0][dd * 128 + cc * 4]) = v;
        }
    }
    __syncthreads();

    const int e = tid & 127;
    float s = 0.f;

    for (int t = 0; t < QTILES; ++t) {
        if (t + 1 < QTILES) {
            const float* src = wbase + (t + 1) * QT * D2;
            const int buf = (t + 1) & 1;
            #pragma unroll
            for (int r = 0; r < 4; ++r) {
                const int j  = tid + 256 * r;
                const int dd = j >> 5;
                const int cc = j & 31;
                float4 v = *(const float4*)(src + dd * D2 + cc * 4);
                *(float4*)(&wt[buf][dd * 128 + cc * 4]) = v;
            }
        }
        if (tid < 128) {
            const float* wrow = &wt[t & 1][e];
            const int dbase = t * QT;
            #pragma unroll
            for (int i = 0; i < QT; ++i)
                s = fmaf(aq[dbase + i], wrow[i * 128], s);
        }
        __syncthreads();
    }
    if (tid < 128) g_q[b * D2 + e0 + e] = s;
}

// ---------------------------------------------------------------------------
// Kernel S: scores + top-10 + small outputs. 8 blocks x 256 threads.
// Dot: 4 threads per k, stride-4 chains + shfl (FP order identical to R2-R4).
// a_s_r staged in smem tiles of 64 k x 64 e (row stride 68 -> conflict-free).
// ---------------------------------------------------------------------------
#define SROW 68         // padded row stride (floats)
#define STILES 10       // 640 / 64

__global__ __launch_bounds__(256) void score_topk_kernel(
    const float* __restrict__ a_s_r,
    const int*   __restrict__ ratings,
    float* __restrict__ out)
{
    __shared__ float q_s[D2];
    __shared__ float sc[Kk];
    __shared__ float at[2][Kk * SROW];

    const int b   = blockIdx.x;
    const int tid = threadIdx.x;

    for (int i = tid; i < D2; i += 256) q_s[i] = g_q[b * D2 + i];

    const float* abase = a_s_r + (size_t)b * Kk * D2;
    {   // preload tile 0: 64 rows x 16 float4 = 1024 f4, 4 per thread
        #pragma unroll
        for (int r = 0; r < 4; ++r) {
            const int j  = tid + 256 * r;
            const int kk = j >> 4;
            const int cc = j & 15;
            float4 v = *(const float4*)(abase + kk * D2 + cc * 4);
            *(float4*)(&at[0][kk * SROW + cc * 4]) = v;
        }
    }
    __syncthreads();

    const int k   = tid >> 2;
    const int sub = tid & 3;
    float s = 0.f;

    for (int t = 0; t < STILES; ++t) {
        if (t + 1 < STILES) {
            const float* src = abase + (t + 1) * 64;
            const int buf = (t + 1) & 1;
            #pragma unroll
            for (int r = 0; r < 4; ++r) {
                const int j  = tid + 256 * r;
                const int kk = j >> 4;
                const int cc = j & 15;
                float4 v = *(const float4*)(src + kk * D2 + cc * 4);
                *(float4*)(&at[buf][kk * SROW + cc * 4]) = v;
            }
        }
        {   // chain steps 16t .. 16t+15 (global e = sub + 4*step)
            const float* arow = &at[t & 1][k * SROW + sub];
            const float* qrow = &q_s[64 * t + sub];
            #pragma unroll
            for (int i = 0; i < 16; ++i)
                s = fmaf(qrow[4 * i], arow[4 * i], s);
        }
        __syncthreads();
    }

    s += __shfl_xor_sync(0xFFFFFFFFu, s, 1);
    s += __shfl_xor_sync(0xFFFFFFFFu, s, 2);
    if (sub == 0) sc[k] = xla_tanhf(s);
    __syncthreads();

    if (tid < 32) {
        const int lane = tid;
        // key = ord(score) << 7 | (127 - k): max key == max score, min index
        unsigned long long k0 =
            ((unsigned long long)ord_f32(sc[lane]) << 7) | (unsigned)(127 - lane);
        unsigned long long k1 =
            ((unsigned long long)ord_f32(sc[lane + 32]) << 7) | (unsigned)(127 - (lane + 32));

        #pragma unroll
        for (int t = 0; t < TOPK; ++t) {
            unsigned long long m = (k0 > k1) ? k0 : k1;
            #pragma unroll
            for (int o = 16; o > 0; o >>= 1) {
                unsigned long long other = __shfl_xor_sync(0xFFFFFFFFu, m, o);
                if (other > m) m = other;
            }
            const int bk = 127 - (int)(m & 127u);
            if (lane == 0) {
                out[OFF_SCORES  + b * TOPK + t] = sc[bk];
                out[OFF_RATINGS + b * TOPK + t] = (float)ratings[b * Kk + bk];
                out[OFF_IDX     + b * TOPK + t] = (float)bk;
                g_topk_idx[b * TOPK + t] = bk;
            }
            if (bk == lane)      k0 = 0ull;
            if (bk == lane + 32) k1 = 0ull;
        }
    }
}

// ---------------------------------------------------------------------------
// Kernel G: fused vectorized gather (unchanged; 26.5us @ 58.8% DRAM)
// ---------------------------------------------------------------------------
__global__ __launch_bounds__(256) void gather_kernel(
    const float4* __restrict__ s_r,
    const float4* __restrict__ h_r,
    const float4* __restrict__ r_a,
    const float4* __restrict__ r_o,
    const float4* __restrict__ mask,
    const int4*   __restrict__ rb,
    const float4* __restrict__ rm,
    const int4*   __restrict__ re,
    float4* __restrict__ out4)
{
    __shared__ int idx_s[Bq * TOPK];
    if (threadIdx.x < Bq * TOPK) idx_s[threadIdx.x] = g_topk_idx[threadIdx.x];
    __syncthreads();

    const unsigned stride = gridDim.x * blockDim.x;
    for (unsigned g = blockIdx.x * blockDim.x + threadIdx.x; g < G_TOTAL; g += stride) {
        if (g >= G_SR_END && g < G_HR_END) {
            const unsigned local = g - G_SR_END;
            const unsigned row = local >> 16;
            const unsigned iv  = local & 0xFFFFu;
            const unsigned b   = row / TOPK;
            const unsigned k   = (unsigned)idx_s[row];
            out4[V4_HR + local] = h_r[(b * Kk + k) * 65536u + iv];
        } else if (g < G_SR_END) {
            const unsigned row = g >> 9;
            const unsigned iv  = g & 511u;
            const unsigned b   = row / TOPK;
            const unsigned k   = (unsigned)idx_s[row];
            out4[V4_SR + g] = s_r[(b * Kk + k) * 512u + iv];
        } else if (g < G_RA_END) {
            const unsigned local = g - G_HR_END;
            const unsigned row = local >> 7;
            const unsigned iv  = local & 127u;
            const unsigned b   = row / TOPK;
            const unsigned k   = (unsigned)idx_s[row];
            out4[V4_RA + local] = r_a[(b * Kk + k) * 128u + iv];
        } else if (g < G_RO_END) {
            const unsigned local = g - G_RA_END;
            const unsigned row = local >> 7;
            const unsigned iv  = local & 127u;
            const unsigned b   = row / TOPK;
            const unsigned k   = (unsigned)idx_s[row];
            out4[V4_RO + local] = r_o[(b * Kk + k) * 128u + iv];
        } else if (g < G_MK_END) {
            const unsigned local = g - G_RO_END;
            const unsigned b = local / TOPK;
            const unsigned k = (unsigned)idx_s[local];
            out4[V4_MASK + local] = mask[b * Kk + k];
        } else if (g < G_RB_END) {
            const unsigned local = g - G_MK_END;
            const unsigned row = local >> 5;
            const unsigned iv  = local & 31u;
            const unsigned b   = row / TOPK;
            const unsigned k   = (unsigned)idx_s[row];
            const int4 v = rb[(b * Kk + k) * 32u + iv];
            out4[V4_RB + local] = make_float4((float)v.x, (float)v.y, (float)v.z, (float)v.w);
        } else if (g < G_RM_END) {
            const unsigned local = g - G_RB_END;
            const unsigned row = local >> 5;
            const unsigned iv  = local & 31u;
            const unsigned b   = row / TOPK;
            const unsigned k   = (unsigned)idx_s[row];
            out4[V4_RM + local] = rm[(b * Kk + k) * 32u + iv];
        } else {
            const unsigned local = g - G_RM_END;
            const unsigned row = local >> 5;
            const unsigned iv  = local & 31u;
            const unsigned b   = row / TOPK;
            const unsigned k   = (unsigned)idx_s[row];
            const int4 v = re[(b * Kk + k) * 32u + iv];
            out4[V4_RE + local] = make_float4((float)v.x, (float)v.y, (float)v.z, (float)v.w);
        }
    }
}

// ---------------------------------------------------------------------------
extern "C" void kernel_launch(void* const* d_in, const int* in_sizes, int n_in,
                              void* d_out, int out_size)
{
    const float* a_s_q   = (const float*)d_in[0];
    const float* a_s_r   = (const float*)d_in[1];
    const float* W       = (const float*)d_in[2];
    const float* s_r     = (const float*)d_in[3];
    const float* h_r     = (const float*)d_in[4];
    const float* r_a     = (const float*)d_in[5];
    const float* r_o     = (const float*)d_in[6];
    const float* mask    = (const float*)d_in[7];
    const int*   rb      = (const int*)d_in[8];
    const float* rm      = (const float*)d_in[9];
    const int*   ratings = (const int*)d_in[10];
    const int*   re      = (const int*)d_in[11];
    float* out = (float*)d_out;

    q_kernel<<<dim3(Bq, 5), 256>>>(a_s_q, W);
    score_topk_kernel<<<Bq, 256>>>(a_s_r, ratings, out);
    gather_kernel<<<4736, 256>>>(
        (const float4*)s_r, (const float4*)h_r, (const float4*)r_a,
        (const float4*)r_o, (const float4*)mask, (const int4*)rb,
        (const float4*)rm, (const int4*)re, (float4*)out);
}

// round 6
// speedup vs baseline: 1.4415x; 1.4415x over previous
#include <cuda_runtime.h>
#include <cuda_bf16.h>
#include <cstdint>

// ---------------------------------------------------------------------------
// Model_70222715289880: bilinear score -> top-k(10/64) -> gather of 10 tensors
// B=8, K=64, TOPK=10, N_R=4, L_R=128, H=512, D=128, D2=640.
//
// R6: 4-stage cp.async.cg ring pipelines for both GEMV phases (R5's depth-2
// LDG->STS pipeline exposed full load latency per tile: 29us). FP summation
// order is BIT-IDENTICAL to the passing R2-R5 kernels.
// ---------------------------------------------------------------------------

#define Bq   8
#define Kk   64
#define TOPK 10
#define D2   640

#define OFF_SCORES   0
#define OFF_RATINGS  21238160
#define OFF_IDX      21248480

// vec4 (float4) offsets of gathered segments in dst
#define V4_SR    20u
#define V4_HR    40980u
#define V4_RA    5283860u
#define V4_RO    5294100u
#define V4_MASK  5304340u
#define V4_RB    5304420u
#define V4_RM    5306980u
#define V4_RE    5309560u

// gather-index range boundaries, in vec4 units
#define G_SR_END   40960u
#define G_HR_END   5283840u
#define G_RA_END   5294080u
#define G_RO_END   5304320u
#define G_MK_END   5304400u
#define G_RB_END   5306960u
#define G_RM_END   5309520u
#define G_RE_END   5312080u
#define G_TOTAL    5312080u

__device__ int   g_topk_idx[Bq * TOPK];
__device__ float g_q[Bq * D2];

// -------------------------------- cp.async --------------------------------
__device__ __forceinline__ void cpa16(uint32_t dst_smem, const void* src) {
    asm volatile("cp.async.cg.shared.global [%0], [%1], 16;"
                 :: "r"(dst_smem), "l"(src));
}
#define CPA_COMMIT() asm volatile("cp.async.commit_group;")
#define CPA_WAIT2()  asm volatile("cp.async.wait_group 2;" ::: "memory")

__device__ __forceinline__ uint32_t smem_u32(const void* p) {
    return (uint32_t)__cvta_generic_to_shared(p);
}

// ---------------------------------------------------------------------------
// XLA's tanh (Eigen generic_fast_tanh_float as emitted by elemental_ir_emitter)
// ---------------------------------------------------------------------------
__device__ __forceinline__ float xla_tanhf(float x)
{
    const float kClamp = 7.90531110763549805f;
    float xc = fmaxf(-kClamp, fminf(x, kClamp));
    float x2 = xc * xc;

    float p = fmaf(x2, -2.76076847742355e-16f, 2.00018790482477e-13f);
    p = fmaf(x2, p, -8.60467152213735e-11f);
    p = fmaf(x2, p,  5.12229709037114e-08f);
    p = fmaf(x2, p,  1.48572235717979e-05f);
    p = fmaf(x2, p,  6.37261928875436e-04f);
    p = fmaf(x2, p,  4.89352455891786e-03f);
    p = xc * p;

    float q = fmaf(x2, 1.19825839466702e-06f, 1.18534705686654e-04f);
    q = fmaf(x2, q, 2.26843463243900e-03f);
    q = fmaf(x2, q, 4.89352518554385e-03f);

    float r = p / q;
    return (fabsf(x) < 0.0004f) ? x : r;
}

// total-order key on float (ascending)
__device__ __forceinline__ unsigned ord_f32(float f)
{
    int i = __float_as_int(f);
    return (i < 0) ? ~(unsigned)i : ((unsigned)i | 0x80000000u);
}

// ---------------------------------------------------------------------------
// Kernel Q: q[b][e] = sum_d a_s_q[b][d] * W[d][e]  (serial-d chain per e).
// Grid (8,5) x 256. 40 tiles of 16 d x 128 e, 4-stage cp.async ring.
// ---------------------------------------------------------------------------
#define QT      16
#define QTILES  40

__global__ __launch_bounds__(256) void q_kernel(
    const float* __restrict__ a_s_q,
    const float* __restrict__ W)
{
    __shared__ float aq[D2];
    __shared__ float wt[4][QT * 128];

    const int b   = blockIdx.x;
    const int e0  = blockIdx.y * 128;
    const int tid = threadIdx.x;

    for (int i = tid; i < D2; i += 256) aq[i] = a_s_q[b * D2 + i];

    const float* wbase = W + e0;
    // per-tile: 512 float4, 2 per thread
    const int dd = tid >> 6;            // j = tid: dd0 = tid>>6? No: j in [0,512)
    // mapping: j = tid + 256*r, dd = j>>5 (0..15), cc = j&31 (0..31)
    // thread's two elements: r=0 -> (tid>>5, tid&31); r=1 -> ((tid+256)>>5, tid&31)
    const int dd0 = tid >> 5;           // 0..7
    const int dd1 = dd0 + 8;            // 8..15
    const int cc  = tid & 31;
    (void)dd;

    const uint32_t wt_base = smem_u32(&wt[0][0]);

    // prologue: tiles 0..2
    #pragma unroll
    for (int p = 0; p < 3; ++p) {
        const float* src = wbase + p * QT * D2;
        cpa16(wt_base + (uint32_t)(p * QT * 128 + dd0 * 128 + cc * 4) * 4u,
              src + dd0 * D2 + cc * 4);
        cpa16(wt_base + (uint32_t)(p * QT * 128 + dd1 * 128 + cc * 4) * 4u,
              src + dd1 * D2 + cc * 4);
        CPA_COMMIT();
    }

    const int e = tid & 127;
    float s = 0.f;

    for (int t = 0; t < QTILES; ++t) {
        CPA_WAIT2();
        __syncthreads();
        if (t + 3 < QTILES) {
            const int buf = (t + 3) & 3;
            const float* src = wbase + (t + 3) * QT * D2;
            cpa16(wt_base + (uint32_t)(buf * QT * 128 + dd0 * 128 + cc * 4) * 4u,
                  src + dd0 * D2 + cc * 4);
            cpa16(wt_base + (uint32_t)(buf * QT * 128 + dd1 * 128 + cc * 4) * 4u,
                  src + dd1 * D2 + cc * 4);
        }
        CPA_COMMIT();
        if (tid < 128) {
            const float* wrow = &wt[t & 3][e];
            const int dbase = t * QT;
            #pragma unroll
            for (int i = 0; i < QT; ++i)
                s = fmaf(aq[dbase + i], wrow[i * 128], s);
        }
    }
    if (tid < 128) g_q[b * D2 + e0 + e] = s;
}

// ---------------------------------------------------------------------------
// Kernel S: scores + top-10 + small outputs. 8 blocks x 256.
// Dot: 4 threads per k, stride-4 chains + shfl (FP order identical to R2-R5).
// a_s_r staged in 20 tiles of 64 k x 32 e, row stride 36, 4-stage ring.
// ---------------------------------------------------------------------------
#define SCT     32      // e per tile
#define SROW    36      // padded row stride (floats)
#define STILES  20      // 640 / 32

__global__ __launch_bounds__(256) void score_topk_kernel(
    const float* __restrict__ a_s_r,
    const int*   __restrict__ ratings,
    float* __restrict__ out)
{
    __shared__ float q_s[D2];
    __shared__ float sc[Kk];
    __shared__ float at[4][Kk * SROW];

    const int b   = blockIdx.x;
    const int tid = threadIdx.x;

    for (int i = tid; i < D2; i += 256) q_s[i] = g_q[b * D2 + i];

    const float* abase = a_s_r + (size_t)b * Kk * D2;
    // per tile: 64 rows x 8 f4 = 512 f4, 2 per thread
    // j = tid + 256*r: kk = j>>3 (0..63), cc = j&7 (0..7)
    const int kk0 = tid >> 3;           // 0..31
    const int kk1 = kk0 + 32;           // 32..63
    const int cc  = tid & 7;

    const uint32_t at_base = smem_u32(&at[0][0]);

    #pragma unroll
    for (int p = 0; p < 3; ++p) {
        const float* src = abase + p * SCT;
        cpa16(at_base + (uint32_t)(p * Kk * SROW + kk0 * SROW + cc * 4) * 4u,
              src + kk0 * D2 + cc * 4);
        cpa16(at_base + (uint32_t)(p * Kk * SROW + kk1 * SROW + cc * 4) * 4u,
              src + kk1 * D2 + cc * 4);
        CPA_COMMIT();
    }

    const int k   = tid >> 2;
    const int sub = tid & 3;
    float s = 0.f;

    for (int t = 0; t < STILES; ++t) {
        CPA_WAIT2();
        __syncthreads();
        if (t + 3 < STILES) {
            const int buf = (t + 3) & 3;
            const float* src = abase + (t + 3) * SCT;
            cpa16(at_base + (uint32_t)(buf * Kk * SROW + kk0 * SROW + cc * 4) * 4u,
                  src + kk0 * D2 + cc * 4);
            cpa16(at_base + (uint32_t)(buf * Kk * SROW + kk1 * SROW + cc * 4) * 4u,
                  src + kk1 * D2 + cc * 4);
        }
        CPA_COMMIT();
        {   // chain steps 8t .. 8t+7 (global e = sub + 4*step)
            const float* arow = &at[t & 3][k * SROW + sub];
            const float* qrow = &q_s[SCT * t + sub];
            #pragma unroll
            for (int i = 0; i < 8; ++i)
                s = fmaf(qrow[4 * i], arow[4 * i], s);
        }
    }

    s += __shfl_xor_sync(0xFFFFFFFFu, s, 1);
    s += __shfl_xor_sync(0xFFFFFFFFu, s, 2);
    if (sub == 0) sc[k] = xla_tanhf(s);
    __syncthreads();

    if (tid < 32) {
        const int lane = tid;
        // key = ord(score) << 7 | (127 - k): max key == max score, min index
        unsigned long long k0 =
            ((unsigned long long)ord_f32(sc[lane]) << 7) | (unsigned)(127 - lane);
        unsigned long long k1 =
            ((unsigned long long)ord_f32(sc[lane + 32]) << 7) | (unsigned)(127 - (lane + 32));

        #pragma unroll
        for (int t = 0; t < TOPK; ++t) {
            unsigned long long m = (k0 > k1) ? k0 : k1;
            #pragma unroll
            for (int o = 16; o > 0; o >>= 1) {
                unsigned long long other = __shfl_xor_sync(0xFFFFFFFFu, m, o);
                if (other > m) m = other;
            }
            const int bk = 127 - (int)(m & 127u);
            if (lane == 0) {
                out[OFF_SCORES  + b * TOPK + t] = sc[bk];
                out[OFF_RATINGS + b * TOPK + t] = (float)ratings[b * Kk + bk];
                out[OFF_IDX     + b * TOPK + t] = (float)bk;
                g_topk_idx[b * TOPK + t] = bk;
            }
            if (bk == lane)      k0 = 0ull;
            if (bk == lane + 32) k1 = 0ull;
        }
    }
}

// ---------------------------------------------------------------------------
// Kernel G: fused vectorized gather (unchanged; 26.5us @ 58.8% DRAM)
// ---------------------------------------------------------------------------
__global__ __launch_bounds__(256) void gather_kernel(
    const float4* __restrict__ s_r,
    const float4* __restrict__ h_r,
    const float4* __restrict__ r_a,
    const float4* __restrict__ r_o,
    const float4* __restrict__ mask,
    const int4*   __restrict__ rb,
    const float4* __restrict__ rm,
    const int4*   __restrict__ re,
    float4* __restrict__ out4)
{
    __shared__ int idx_s[Bq * TOPK];
    if (threadIdx.x < Bq * TOPK) idx_s[threadIdx.x] = g_topk_idx[threadIdx.x];
    __syncthreads();

    const unsigned stride = gridDim.x * blockDim.x;
    for (unsigned g = blockIdx.x * blockDim.x + threadIdx.x; g < G_TOTAL; g += stride) {
        if (g >= G_SR_END && g < G_HR_END) {
            const unsigned local = g - G_SR_END;
            const unsigned row = local >> 16;
            const unsigned iv  = local & 0xFFFFu;
            const unsigned b   = row / TOPK;
            const unsigned k   = (unsigned)idx_s[row];
            out4[V4_HR + local] = h_r[(b * Kk + k) * 65536u + iv];
        } else if (g < G_SR_END) {
            const unsigned row = g >> 9;
            const unsigned iv  = g & 511u;
            const unsigned b   = row / TOPK;
            const unsigned k   = (unsigned)idx_s[row];
            out4[V4_SR + g] = s_r[(b * Kk + k) * 512u + iv];
        } else if (g < G_RA_END) {
            const unsigned local = g - G_HR_END;
            const unsigned row = local >> 7;
            const unsigned iv  = local & 127u;
            const unsigned b   = row / TOPK;
            const unsigned k   = (unsigned)idx_s[row];
            out4[V4_RA + local] = r_a[(b * Kk + k) * 128u + iv];
        } else if (g < G_RO_END) {
            const unsigned local = g - G_RA_END;
            const unsigned row = local >> 7;
            const unsigned iv  = local & 127u;
            const unsigned b   = row / TOPK;
            const unsigned k   = (unsigned)idx_s[row];
            out4[V4_RO + local] = r_o[(b * Kk + k) * 128u + iv];
        } else if (g < G_MK_END) {
            const unsigned local = g - G_RO_END;
            const unsigned b = local / TOPK;
            const unsigned k = (unsigned)idx_s[local];
            out4[V4_MASK + local] = mask[b * Kk + k];
        } else if (g < G_RB_END) {
            const unsigned local = g - G_MK_END;
            const unsigned row = local >> 5;
            const unsigned iv  = local & 31u;
            const unsigned b   = row / TOPK;
            const unsigned k   = (unsigned)idx_s[row];
            const int4 v = rb[(b * Kk + k) * 32u + iv];
            out4[V4_RB + local] = make_float4((float)v.x, (float)v.y, (float)v.z, (float)v.w);
        } else if (g < G_RM_END) {
            const unsigned local = g - G_RB_END;
            const unsigned row = local >> 5;
            const unsigned iv  = local & 31u;
            const unsigned b   = row / TOPK;
            const unsigned k   = (unsigned)idx_s[row];
            out4[V4_RM + local] = rm[(b * Kk + k) * 32u + iv];
        } else {
            const unsigned local = g - G_RM_END;
            const unsigned row = local >> 5;
            const unsigned iv  = local & 31u;
            const unsigned b   = row / TOPK;
            const unsigned k   = (unsigned)idx_s[row];
            const int4 v = re[(b * Kk + k) * 32u + iv];
            out4[V4_RE + local] = make_float4((float)v.x, (float)v.y, (float)v.z, (float)v.w);
        }
    }
}

// ---------------------------------------------------------------------------
extern "C" void kernel_launch(void* const* d_in, const int* in_sizes, int n_in,
                              void* d_out, int out_size)
{
    const float* a_s_q   = (const float*)d_in[0];
    const float* a_s_r   = (const float*)d_in[1];
    const float* W       = (const float*)d_in[2];
    const float* s_r     = (const float*)d_in[3];
    const float* h_r     = (const float*)d_in[4];
    const float* r_a     = (const float*)d_in[5];
    const float* r_o     = (const float*)d_in[6];
    const float* mask    = (const float*)d_in[7];
    const int*   rb      = (const int*)d_in[8];
    const float* rm      = (const float*)d_in[9];
    const int*   ratings = (const int*)d_in[10];
    const int*   re      = (const int*)d_in[11];
    float* out = (float*)d_out;

    q_kernel<<<dim3(Bq, 5), 256>>>(a_s_q, W);
    score_topk_kernel<<<Bq, 256>>>(a_s_r, ratings, out);
    gather_kernel<<<4736, 256>>>(
        (const float4*)s_r, (const float4*)h_r, (const float4*)r_a,
        (const float4*)r_o, (const float4*)mask, (const int4*)rb,
        (const float4*)rm, (const int4*)re, (float4*)out);
}

// round 7
// speedup vs baseline: 1.7853x; 1.2385x over previous
#include <cuda_runtime.h>
#include <cuda_bf16.h>
#include <cstdint>

// ---------------------------------------------------------------------------
// Model_70222715289880: bilinear score -> top-k(10/64) -> gather of 10 tensors
// B=8, K=64, TOPK=10, N_R=4, L_R=128, H=512, D=128, D2=640.
//
// R7: barrier-free warp-owned cp.async pipelines (5 stages, 4 tiles in
// flight, __syncwarp instead of __syncthreads) for both GEMV phases, and a
// branch-free dedicated path for the dominant h_r copy in the gather.
// FP summation order is BIT-IDENTICAL to the passing R2-R6 kernels.
// ---------------------------------------------------------------------------

#define Bq   8
#define Kk   64
#define TOPK 10
#define D2   640

#define OFF_SCORES   0
#define OFF_RATINGS  21238160
#define OFF_IDX      21248480

// vec4 (float4) offsets of gathered segments in dst
#define V4_SR    20u
#define V4_HR    40980u
#define V4_RA    5283860u
#define V4_RO    5294100u
#define V4_MASK  5304340u
#define V4_RB    5304420u
#define V4_RM    5306980u
#define V4_RE    5309560u

// small-gather compacted ranges (f4 units), h_r excluded
#define SM_SR_END  40960u
#define SM_RA_END  51200u
#define SM_RO_END  61440u
#define SM_MK_END  61520u
#define SM_RB_END  64080u
#define SM_RM_END  66640u
#define SM_TOTAL   69200u

#define HR_BLOCKS  5120    // 80 rows * 64 chunks
#define SM_BLOCKS  128

__device__ int   g_topk_idx[Bq * TOPK];
__device__ float g_q[Bq * D2];

// -------------------------------- cp.async --------------------------------
__device__ __forceinline__ void cpa16(uint32_t dst_smem, const void* src) {
    asm volatile("cp.async.cg.shared.global [%0], [%1], 16;"
                 :: "r"(dst_smem), "l"(src));
}
#define CPA_COMMIT() asm volatile("cp.async.commit_group;")
#define CPA_WAIT3()  asm volatile("cp.async.wait_group 3;" ::: "memory")

__device__ __forceinline__ uint32_t smem_u32(const void* p) {
    return (uint32_t)__cvta_generic_to_shared(p);
}

// ---------------------------------------------------------------------------
// XLA's tanh (Eigen generic_fast_tanh_float as emitted by elemental_ir_emitter)
// ---------------------------------------------------------------------------
__device__ __forceinline__ float xla_tanhf(float x)
{
    const float kClamp = 7.90531110763549805f;
    float xc = fmaxf(-kClamp, fminf(x, kClamp));
    float x2 = xc * xc;

    float p = fmaf(x2, -2.76076847742355e-16f, 2.00018790482477e-13f);
    p = fmaf(x2, p, -8.60467152213735e-11f);
    p = fmaf(x2, p,  5.12229709037114e-08f);
    p = fmaf(x2, p,  1.48572235717979e-05f);
    p = fmaf(x2, p,  6.37261928875436e-04f);
    p = fmaf(x2, p,  4.89352455891786e-03f);
    p = xc * p;

    float q = fmaf(x2, 1.19825839466702e-06f, 1.18534705686654e-04f);
    q = fmaf(x2, q, 2.26843463243900e-03f);
    q = fmaf(x2, q, 4.89352518554385e-03f);

    float r = p / q;
    return (fabsf(x) < 0.0004f) ? x : r;
}

// total-order key on float (ascending)
__device__ __forceinline__ unsigned ord_f32(float f)
{
    int i = __float_as_int(f);
    return (i < 0) ? ~(unsigned)i : ((unsigned)i | 0x80000000u);
}

// ---------------------------------------------------------------------------
// Kernel Q: q[b][e] = sum_d a_s_q[b][d] * W[d][e]  (serial-d chain per e).
// Grid (8,5) x 128 threads (4 warps). Warp w owns e-slice [32w, 32w+32).
// 40 tiles of 16 d, 5-stage warp-private cp.async ring, NO block barriers
// in the main loop.
// ---------------------------------------------------------------------------
#define QT      16
#define QTILES  40
#define QST     5

__global__ __launch_bounds__(128) void q_kernel(
    const float* __restrict__ a_s_q,
    const float* __restrict__ W)
{
    __shared__ float aq[D2];
    __shared__ float wt[QST][4][QT * 32];   // [stage][warp][row*32 + e_local]

    const int b   = blockIdx.x;
    const int e0  = blockIdx.y * 128;
    const int tid = threadIdx.x;
    const int w   = tid >> 5;
    const int l   = tid & 31;

    for (int i = tid; i < D2; i += 128) aq[i] = a_s_q[b * D2 + i];
    __syncthreads();   // only block-wide sync; main loop is warp-private

    const int rrow = l >> 3;        // 0..3
    const int c8   = l & 7;         // 0..7
    // per-tile: 4 cp.async per lane; instr r covers rows 4r+rrow
    const float* gsrc0 = W + e0 + w * 32 + c8 * 4 + rrow * D2;
    const uint32_t sbase = smem_u32(&wt[0][0][0])
                         + (uint32_t)w * (QT * 32 * 4)
                         + (uint32_t)rrow * (32 * 4)
                         + (uint32_t)c8 * 16;

#define Q_ISSUE(T, ST)                                                        \
    {                                                                         \
        const float* _s = gsrc0 + (T) * QT * D2;                              \
        const uint32_t _d = sbase + (uint32_t)(ST) * (4 * QT * 32 * 4);       \
        cpa16(_d + 0 * 512, _s + 0 * 4 * D2);                                 \
        cpa16(_d + 1 * 512, _s + 1 * 4 * D2);                                 \
        cpa16(_d + 2 * 512, _s + 2 * 4 * D2);                                 \
        cpa16(_d + 3 * 512, _s + 3 * 4 * D2);                                 \
        CPA_COMMIT();                                                         \
    }

    Q_ISSUE(0, 0) Q_ISSUE(1, 1) Q_ISSUE(2, 2) Q_ISSUE(3, 3)

    float s = 0.f;
    int st = 0, nst = 4;
    for (int t = 0; t < QTILES; ++t) {
        CPA_WAIT3();
        __syncwarp();
        if (t + 4 < QTILES) { Q_ISSUE(t + 4, nst) } else { CPA_COMMIT(); }
        const float* wrow = &wt[st][w][l];
        const int dbase = t * QT;
        #pragma unroll
        for (int i = 0; i < QT; ++i)
            s = fmaf(aq[dbase + i], wrow[i * 32], s);
        if (++st == QST) st = 0;
        if (++nst == QST) nst = 0;
    }
    g_q[b * D2 + e0 + w * 32 + l] = s;
#undef Q_ISSUE
}

// ---------------------------------------------------------------------------
// Kernel S: scores + top-10 + small outputs. 8 blocks x 256 threads (8 warps).
// Warp w owns k in [8w, 8w+8). 20 tiles of 32 e, 5-stage warp-private ring.
// Dot FP order identical to R2-R6 (4 threads per k, stride-4, shfl 1 then 2).
// ---------------------------------------------------------------------------
#define SCT     32      // e per tile
#define SROW    36      // padded row stride (floats) -> conflict-free LDS
#define STILES  20
#define SST     5

__global__ __launch_bounds__(256) void score_topk_kernel(
    const float* __restrict__ a_s_r,
    const int*   __restrict__ ratings,
    float* __restrict__ out)
{
    __shared__ float q_s[D2];
    __shared__ float sc[Kk];
    __shared__ float at[SST][8][8 * SROW];   // [stage][warp][k_local*36 + e]

    const int b   = blockIdx.x;
    const int tid = threadIdx.x;
    const int w   = tid >> 5;
    const int l   = tid & 31;

    for (int i = tid; i < D2; i += 256) q_s[i] = g_q[b * D2 + i];
    __syncthreads();

    const float* abase = a_s_r + (size_t)b * Kk * D2;
    const int rrow = l >> 3;        // 0..3
    const int c8   = l & 7;         // 0..7
    // per tile: 2 cp.async per lane; instr r covers k_local = 4r + rrow
    const float* gsrc0 = abase + (w * 8 + rrow) * D2 + c8 * 4;
    const uint32_t sbase = smem_u32(&at[0][0][0])
                         + (uint32_t)w * (8 * SROW * 4)
                         + (uint32_t)rrow * (SROW * 4)
                         + (uint32_t)c8 * 16;

#define S_ISSUE(T, ST)                                                        \
    {                                                                         \
        const float* _s = gsrc0 + (T) * SCT;                                  \
        const uint32_t _d = sbase + (uint32_t)(ST) * (8 * 8 * SROW * 4);      \
        cpa16(_d,                 _s);                                        \
        cpa16(_d + 4 * SROW * 4,  _s + 4 * D2);                               \
        CPA_COMMIT();                                                         \
    }

    S_ISSUE(0, 0) S_ISSUE(1, 1) S_ISSUE(2, 2) S_ISSUE(3, 3)

    const int k   = tid >> 2;
    const int sub = tid & 3;
    const int kloc = k & 7;
    float s = 0.f;
    int st = 0, nst = 4;
    for (int t = 0; t < STILES; ++t) {
        CPA_WAIT3();
        __syncwarp();
        if (t + 4 < STILES) { S_ISSUE(t + 4, nst) } else { CPA_COMMIT(); }
        const float* arow = &at[st][w][kloc * SROW + sub];
        const float* qrow = &q_s[SCT * t + sub];
        #pragma unroll
        for (int i = 0; i < 8; ++i)
            s = fmaf(qrow[4 * i], arow[4 * i], s);
        if (++st == SST) st = 0;
        if (++nst == SST) nst = 0;
    }
#undef S_ISSUE

    s += __shfl_xor_sync(0xFFFFFFFFu, s, 1);
    s += __shfl_xor_sync(0xFFFFFFFFu, s, 2);
    if (sub == 0) sc[k] = xla_tanhf(s);
    __syncthreads();

    if (tid < 32) {
        const int lane = tid;
        // key = ord(score) << 7 | (127 - k): max key == max score, min index
        unsigned long long k0 =
            ((unsigned long long)ord_f32(sc[lane]) << 7) | (unsigned)(127 - lane);
        unsigned long long k1 =
            ((unsigned long long)ord_f32(sc[lane + 32]) << 7) | (unsigned)(127 - (lane + 32));

        #pragma unroll
        for (int t = 0; t < TOPK; ++t) {
            unsigned long long m = (k0 > k1) ? k0 : k1;
            #pragma unroll
            for (int o = 16; o > 0; o >>= 1) {
                unsigned long long other = __shfl_xor_sync(0xFFFFFFFFu, m, o);
                if (other > m) m = other;
            }
            const int bk = 127 - (int)(m & 127u);
            if (lane == 0) {
                out[OFF_SCORES  + b * TOPK + t] = sc[bk];
                out[OFF_RATINGS + b * TOPK + t] = (float)ratings[b * Kk + bk];
                out[OFF_IDX     + b * TOPK + t] = (float)bk;
                g_topk_idx[b * TOPK + t] = bk;
            }
            if (bk == lane)      k0 = 0ull;
            if (bk == lane + 32) k1 = 0ull;
        }
    }
}

// ---------------------------------------------------------------------------
// Kernel G: gather. Blocks [0, 5120): branch-free h_r copy (row = bid>>6,
// chunk = bid&63, 16KB per block, 4 independent f4 ld/st per thread with
// streaming hints). Blocks [5120, 5248): grid-stride over the small segments.
// ---------------------------------------------------------------------------
__global__ __launch_bounds__(256) void gather_kernel(
    const float4* __restrict__ s_r,
    const float4* __restrict__ h_r,
    const float4* __restrict__ r_a,
    const float4* __restrict__ r_o,
    const float4* __restrict__ mask,
    const int4*   __restrict__ rb,
    const float4* __restrict__ rm,
    const int4*   __restrict__ re,
    float4* __restrict__ out4)
{
    __shared__ int idx_s[Bq * TOPK];
    if (threadIdx.x < Bq * TOPK) idx_s[threadIdx.x] = g_topk_idx[threadIdx.x];
    __syncthreads();

    if (blockIdx.x < HR_BLOCKS) {
        const unsigned row   = blockIdx.x >> 6;          // 0..79
        const unsigned chunk = blockIdx.x & 63u;
        const unsigned b     = row / TOPK;
        const unsigned k     = (unsigned)idx_s[row];
        const float4* src = h_r + (b * Kk + k) * 65536u + chunk * 1024u + threadIdx.x;
        float4*       dst = out4 + V4_HR + row * 65536u + chunk * 1024u + threadIdx.x;
        float4 v0 = __ldcs(src);
        float4 v1 = __ldcs(src + 256);
        float4 v2 = __ldcs(src + 512);
        float4 v3 = __ldcs(src + 768);
        __stcs(dst,       v0);
        __stcs(dst + 256, v1);
        __stcs(dst + 512, v2);
        __stcs(dst + 768, v3);
        return;
    }

    const unsigned stride = SM_BLOCKS * 256u;
    for (unsigned g = (blockIdx.x - HR_BLOCKS) * 256u + threadIdx.x;
         g < SM_TOTAL; g += stride) {
        if (g < SM_SR_END) {
            const unsigned row = g >> 9;
            const unsigned iv  = g & 511u;
            const unsigned b   = row / TOPK;
            const unsigned k   = (unsigned)idx_s[row];
            out4[V4_SR + g] = s_r[(b * Kk + k) * 512u + iv];
        } else if (g < SM_RA_END) {
            const unsigned local = g - SM_SR_END;
            const unsigned row = local >> 7;
            const unsigned iv  = local & 127u;
            const unsigned b   = row / TOPK;
            const unsigned k   = (unsigned)idx_s[row];
            out4[V4_RA + local] = r_a[(b * Kk + k) * 128u + iv];
        } else if (g < SM_RO_END) {
            const unsigned local = g - SM_RA_END;
            const unsigned row = local >> 7;
            const unsigned iv  = local & 127u;
            const unsigned b   = row / TOPK;
            const unsigned k   = (unsigned)idx_s[row];
            out4[V4_RO + local] = r_o[(b * Kk + k) * 128u + iv];
        } else if (g < SM_MK_END) {
            const unsigned local = g - SM_RO_END;   // == row
            const unsigned b = local / TOPK;
            const unsigned k = (unsigned)idx_s[local];
            out4[V4_MASK + local] = mask[b * Kk + k];
        } else if (g < SM_RB_END) {
            const unsigned local = g - SM_MK_END;
            const unsigned row = local >> 5;
            const unsigned iv  = local & 31u;
            const unsigned b   = row / TOPK;
            const unsigned k   = (unsigned)idx_s[row];
            const int4 v = rb[(b * Kk + k) * 32u + iv];
            out4[V4_RB + local] = make_float4((float)v.x, (float)v.y, (float)v.z, (float)v.w);
        } else if (g < SM_RM_END) {
            const unsigned local = g - SM_RB_END;
            const unsigned row = local >> 5;
            const unsigned iv  = local & 31u;
            const unsigned b   = row / TOPK;
            const unsigned k   = (unsigned)idx_s[row];
            out4[V4_RM + local] = rm[(b * Kk + k) * 32u + iv];
        } else {
            const unsigned local = g - SM_RM_END;
            const unsigned row = local >> 5;
            const unsigned iv  = local & 31u;
            const unsigned b   = row / TOPK;
            const unsigned k   = (unsigned)idx_s[row];
            const int4 v = re[(b * Kk + k) * 32u + iv];
            out4[V4_RE + local] = make_float4((float)v.x, (float)v.y, (float)v.z, (float)v.w);
        }
    }
}

// ---------------------------------------------------------------------------
extern "C" void kernel_launch(void* const* d_in, const int* in_sizes, int n_in,
                              void* d_out, int out_size)
{
    const float* a_s_q   = (const float*)d_in[0];
    const float* a_s_r   = (const float*)d_in[1];
    const float* W       = (const float*)d_in[2];
    const float* s_r     = (const float*)d_in[3];
    const float* h_r     = (const float*)d_in[4];
    const float* r_a     = (const float*)d_in[5];
    const float* r_o     = (const float*)d_in[6];
    const float* mask    = (const float*)d_in[7];
    const int*   rb      = (const int*)d_in[8];
    const float* rm      = (const float*)d_in[9];
    const int*   ratings = (const int*)d_in[10];
    const int*   re      = (const int*)d_in[11];
    float* out = (float*)d_out;

    q_kernel<<<dim3(Bq, 5), 128>>>(a_s_q, W);
    score_topk_kernel<<<Bq, 256>>>(a_s_r, ratings, out);
    gather_kernel<<<HR_BLOCKS + SM_BLOCKS, 256>>>(
        (const float4*)s_r, (const float4*)h_r, (const float4*)r_a,
        (const float4*)r_o, (const float4*)mask, (const int4*)rb,
        (const float4*)rm, (const int4*)re, (float4*)out);
}

// round 8
// speedup vs baseline: 1.7963x; 1.0062x over previous
#include <cuda_runtime.h>
#include <cuda_bf16.h>
#include <cstdint>

// ---------------------------------------------------------------------------
// Model_70222715289880: bilinear score -> top-k(10/64) -> gather of 10 tensors
// B=8, K=64, TOPK=10, N_R=4, L_R=128, H=512, D=128, D2=640.
//
// R8: DEEP cp.async rings (12-stage q / 10-stage score, ~100KB dynamic smem)
// — cp.async has no depth cap on sm_103a; R7's 4-stage ring left only ~8KB
// in flight per warp, far too little to cover the cold-DRAM latency of W
// (W is evicted from L2 every replay by the 168MB gather stream).
// FP summation order is BIT-IDENTICAL to the passing R2-R7 kernels.
// ---------------------------------------------------------------------------

#define Bq   8
#define Kk   64
#define TOPK 10
#define D2   640

#define OFF_SCORES   0
#define OFF_RATINGS  21238160
#define OFF_IDX      21248480

// vec4 (float4) offsets of gathered segments in dst
#define V4_SR    20u
#define V4_HR    40980u
#define V4_RA    5283860u
#define V4_RO    5294100u
#define V4_MASK  5304340u
#define V4_RB    5304420u
#define V4_RM    5306980u
#define V4_RE    5309560u

// small-gather compacted ranges (f4 units), h_r excluded
#define SM_SR_END  40960u
#define SM_RA_END  51200u
#define SM_RO_END  61440u
#define SM_MK_END  61520u
#define SM_RB_END  64080u
#define SM_RM_END  66640u
#define SM_TOTAL   69200u

#define HR_BLOCKS  5120    // 80 rows * 64 chunks
#define SM_BLOCKS  128

__device__ int   g_topk_idx[Bq * TOPK];
__device__ float g_q[Bq * D2];

// -------------------------------- cp.async --------------------------------
__device__ __forceinline__ void cpa16(uint32_t dst_smem, const void* src) {
    asm volatile("cp.async.cg.shared.global [%0], [%1], 16;"
                 :: "r"(dst_smem), "l"(src));
}
#define CPA_COMMIT()  asm volatile("cp.async.commit_group;")
#define CPA_WAIT(N)   asm volatile("cp.async.wait_group %0;" :: "n"(N) : "memory")

__device__ __forceinline__ uint32_t smem_u32(const void* p) {
    return (uint32_t)__cvta_generic_to_shared(p);
}

// ---------------------------------------------------------------------------
// XLA's tanh (Eigen generic_fast_tanh_float as emitted by elemental_ir_emitter)
// ---------------------------------------------------------------------------
__device__ __forceinline__ float xla_tanhf(float x)
{
    const float kClamp = 7.90531110763549805f;
    float xc = fmaxf(-kClamp, fminf(x, kClamp));
    float x2 = xc * xc;

    float p = fmaf(x2, -2.76076847742355e-16f, 2.00018790482477e-13f);
    p = fmaf(x2, p, -8.60467152213735e-11f);
    p = fmaf(x2, p,  5.12229709037114e-08f);
    p = fmaf(x2, p,  1.48572235717979e-05f);
    p = fmaf(x2, p,  6.37261928875436e-04f);
    p = fmaf(x2, p,  4.89352455891786e-03f);
    p = xc * p;

    float q = fmaf(x2, 1.19825839466702e-06f, 1.18534705686654e-04f);
    q = fmaf(x2, q, 2.26843463243900e-03f);
    q = fmaf(x2, q, 4.89352518554385e-03f);

    float r = p / q;
    return (fabsf(x) < 0.0004f) ? x : r;
}

// total-order key on float (ascending)
__device__ __forceinline__ unsigned ord_f32(float f)
{
    int i = __float_as_int(f);
    return (i < 0) ? ~(unsigned)i : ((unsigned)i | 0x80000000u);
}

// ---------------------------------------------------------------------------
// Kernel Q: q[b][e] = sum_d a_s_q[b][d] * W[d][e]  (serial-d chain per e).
// Grid (8,5) x 128 threads (4 warps). Warp w owns e-slice [32w, 32w+32).
// 40 tiles of 16 d; 12-stage warp-private cp.async ring (11 tiles = 22KB
// in flight per warp). Dynamic smem: 640 + 12*4*512 floats = 100,864 B.
// ---------------------------------------------------------------------------
#define QT       16
#define QTILES   40
#define QST      12
#define Q_SMEM   ((D2 + QST * 4 * QT * 32) * 4)

__global__ __launch_bounds__(128) void q_kernel(
    const float* __restrict__ a_s_q,
    const float* __restrict__ W)
{
    extern __shared__ float dynq[];
    float* aq = dynq;              // [640]
    float* wt = dynq + D2;         // [QST][4][QT*32]

    const int b   = blockIdx.x;
    const int e0  = blockIdx.y * 128;
    const int tid = threadIdx.x;
    const int w   = tid >> 5;
    const int l   = tid & 31;

    for (int i = tid; i < D2; i += 128) aq[i] = a_s_q[b * D2 + i];
    __syncthreads();   // only block-wide sync; main loop is warp-private

    const int rrow = l >> 3;        // 0..3
    const int c8   = l & 7;         // 0..7
    // per-tile: 4 cp.async per lane; instr i covers rows 4i + rrow
    const float* gsrc0 = W + e0 + w * 32 + c8 * 4 + rrow * D2;
    const uint32_t sbase = smem_u32(wt)
                         + (uint32_t)w * (QT * 32 * 4)      // 2048 B / warp
                         + (uint32_t)rrow * (32 * 4)        // 128 B / row
                         + (uint32_t)c8 * 16;

#define Q_ISSUE(T, ST)                                                        \
    {                                                                         \
        const float* _s = gsrc0 + (T) * QT * D2;                              \
        const uint32_t _d = sbase + (uint32_t)(ST) * (4 * QT * 32 * 4);       \
        cpa16(_d + 0 * 512, _s + 0 * 4 * D2);                                 \
        cpa16(_d + 1 * 512, _s + 1 * 4 * D2);                                 \
        cpa16(_d + 2 * 512, _s + 2 * 4 * D2);                                 \
        cpa16(_d + 3 * 512, _s + 3 * 4 * D2);                                 \
        CPA_COMMIT();                                                         \
    }

    // prologue: tiles 0..10 into stages 0..10 (11 groups in flight)
    #pragma unroll
    for (int p = 0; p < QST - 1; ++p) Q_ISSUE(p, p)

    float s = 0.f;
    int st = 0, nst = QST - 1;
    for (int t = 0; t < QTILES; ++t) {
        CPA_WAIT(QST - 2);          // allow 10 pending -> oldest tile done
        __syncwarp();
        if (t + QST - 1 < QTILES) { Q_ISSUE(t + QST - 1, nst) } else { CPA_COMMIT(); }
        const float* wrow = &wt[(st * 4 + w) * (QT * 32) + l];
        const int dbase = t * QT;
        #pragma unroll
        for (int i = 0; i < QT; ++i)
            s = fmaf(aq[dbase + i], wrow[i * 32], s);
        if (++st == QST) st = 0;
        if (++nst == QST) nst = 0;
    }
    g_q[b * D2 + e0 + w * 32 + l] = s;
#undef Q_ISSUE
}

// ---------------------------------------------------------------------------
// Kernel S: scores + top-10 + small outputs. 8 blocks x 256 threads (8 warps).
// Warp w owns k in [8w, 8w+8). 20 tiles of 32 e; 10-stage warp-private ring.
// Dot FP order identical to R2-R7 (4 threads per k, stride-4, shfl 1 then 2).
// Dynamic smem: 640 + 10*8*288 floats = 94,720 B.
// ---------------------------------------------------------------------------
#define SCT      32      // e per tile
#define SROW     36      // padded row stride (floats) -> conflict-free LDS
#define STILES   20
#define SST      10
#define S_SMEM   ((D2 + SST * 8 * 8 * SROW) * 4)

__global__ __launch_bounds__(256) void score_topk_kernel(
    const float* __restrict__ a_s_r,
    const int*   __restrict__ ratings,
    float* __restrict__ out)
{
    __shared__ float sc[Kk];
    extern __shared__ float dyns[];
    float* q_s = dyns;             // [640]
    float* at  = dyns + D2;        // [SST][8][8*SROW]

    const int b   = blockIdx.x;
    const int tid = threadIdx.x;
    const int w   = tid >> 5;
    const int l   = tid & 31;

    for (int i = tid; i < D2; i += 256) q_s[i] = g_q[b * D2 + i];
    __syncthreads();

    const float* abase = a_s_r + (size_t)b * Kk * D2;
    const int rrow = l >> 3;        // 0..3  (covers k_local rrow and rrow+4)
    const int c8   = l & 7;         // 0..7
    const float* gsrc0 = abase + (w * 8 + rrow) * D2 + c8 * 4;
    const uint32_t sbase = smem_u32(at)
                         + (uint32_t)w * (8 * SROW * 4)     // 1152 B / warp
                         + (uint32_t)rrow * (SROW * 4)      // 144 B / row
                         + (uint32_t)c8 * 16;

#define S_ISSUE(T, ST)                                                        \
    {                                                                         \
        const float* _s = gsrc0 + (T) * SCT;                                  \
        const uint32_t _d = sbase + (uint32_t)(ST) * (8 * 8 * SROW * 4);      \
        cpa16(_d,                _s);                                         \
        cpa16(_d + 4 * SROW * 4, _s + 4 * D2);                                \
        CPA_COMMIT();                                                         \
    }

    // prologue: tiles 0..8 into stages 0..8 (9 groups in flight)
    #pragma unroll
    for (int p = 0; p < SST - 1; ++p) S_ISSUE(p, p)

    const int k    = tid >> 2;
    const int sub  = tid & 3;
    const int kloc = k & 7;
    float s = 0.f;
    int st = 0, nst = SST - 1;
    for (int t = 0; t < STILES; ++t) {
        CPA_WAIT(SST - 2);
        __syncwarp();
        if (t + SST - 1 < STILES) { S_ISSUE(t + SST - 1, nst) } else { CPA_COMMIT(); }
        const float* arow = &at[(st * 8 + w) * (8 * SROW) + kloc * SROW + sub];
        const float* qrow = &q_s[SCT * t + sub];
        #pragma unroll
        for (int i = 0; i < 8; ++i)
            s = fmaf(qrow[4 * i], arow[4 * i], s);
        if (++st == SST) st = 0;
        if (++nst == SST) nst = 0;
    }
#undef S_ISSUE

    s += __shfl_xor_sync(0xFFFFFFFFu, s, 1);
    s += __shfl_xor_sync(0xFFFFFFFFu, s, 2);
    if (sub == 0) sc[k] = xla_tanhf(s);
    __syncthreads();

    if (tid < 32) {
        const int lane = tid;
        // key = ord(score) << 7 | (127 - k): max key == max score, min index
        unsigned long long k0 =
            ((unsigned long long)ord_f32(sc[lane]) << 7) | (unsigned)(127 - lane);
        unsigned long long k1 =
            ((unsigned long long)ord_f32(sc[lane + 32]) << 7) | (unsigned)(127 - (lane + 32));

        #pragma unroll
        for (int t = 0; t < TOPK; ++t) {
            unsigned long long m = (k0 > k1) ? k0 : k1;
            #pragma unroll
            for (int o = 16; o > 0; o >>= 1) {
                unsigned long long other = __shfl_xor_sync(0xFFFFFFFFu, m, o);
                if (other > m) m = other;
            }
            const int bk = 127 - (int)(m & 127u);
            if (lane == 0) {
                out[OFF_SCORES  + b * TOPK + t] = sc[bk];
                out[OFF_RATINGS + b * TOPK + t] = (float)ratings[b * Kk + bk];
                out[OFF_IDX     + b * TOPK + t] = (float)bk;
                g_topk_idx[b * TOPK + t] = bk;
            }
            if (bk == lane)      k0 = 0ull;
            if (bk == lane + 32) k1 = 0ull;
        }
    }
}

// ---------------------------------------------------------------------------
// Kernel G: gather. Blocks [0, 5120): branch-free h_r copy (16KB/block,
// 4 independent f4 ld/st per thread, streaming hints). Blocks [5120, 5248):
// grid-stride over the small segments. (Unchanged from R7.)
// ---------------------------------------------------------------------------
__global__ __launch_bounds__(256) void gather_kernel(
    const float4* __restrict__ s_r,
    const float4* __restrict__ h_r,
    const float4* __restrict__ r_a,
    const float4* __restrict__ r_o,
    const float4* __restrict__ mask,
    const int4*   __restrict__ rb,
    const float4* __restrict__ rm,
    const int4*   __restrict__ re,
    float4* __restrict__ out4)
{
    __shared__ int idx_s[Bq * TOPK];
    if (threadIdx.x < Bq * TOPK) idx_s[threadIdx.x] = g_topk_idx[threadIdx.x];
    __syncthreads();

    if (blockIdx.x < HR_BLOCKS) {
        const unsigned row   = blockIdx.x >> 6;          // 0..79
        const unsigned chunk = blockIdx.x & 63u;
        const unsigned b     = row / TOPK;
        const unsigned k     = (unsigned)idx_s[row];
        const float4* src = h_r + (b * Kk + k) * 65536u + chunk * 1024u + threadIdx.x;
        float4*       dst = out4 + V4_HR + row * 65536u + chunk * 1024u + threadIdx.x;
        float4 v0 = __ldcs(src);
        float4 v1 = __ldcs(src + 256);
        float4 v2 = __ldcs(src + 512);
        float4 v3 = __ldcs(src + 768);
        __stcs(dst,       v0);
        __stcs(dst + 256, v1);
        __stcs(dst + 512, v2);
        __stcs(dst + 768, v3);
        return;
    }

    const unsigned stride = SM_BLOCKS * 256u;
    for (unsigned g = (blockIdx.x - HR_BLOCKS) * 256u + threadIdx.x;
         g < SM_TOTAL; g += stride) {
        if (g < SM_SR_END) {
            const unsigned row = g >> 9;
            const unsigned iv  = g & 511u;
            const unsigned b   = row / TOPK;
            const unsigned k   = (unsigned)idx_s[row];
            out4[V4_SR + g] = s_r[(b * Kk + k) * 512u + iv];
        } else if (g < SM_RA_END) {
            const unsigned local = g - SM_SR_END;
            const unsigned row = local >> 7;
            const unsigned iv  = local & 127u;
            const unsigned b   = row / TOPK;
            const unsigned k   = (unsigned)idx_s[row];
            out4[V4_RA + local] = r_a[(b * Kk + k) * 128u + iv];
        } else if (g < SM_RO_END) {
            const unsigned local = g - SM_RA_END;
            const unsigned row = local >> 7;
            const unsigned iv  = local & 127u;
            const unsigned b   = row / TOPK;
            const unsigned k   = (unsigned)idx_s[row];
            out4[V4_RO + local] = r_o[(b * Kk + k) * 128u + iv];
        } else if (g < SM_MK_END) {
            const unsigned local = g - SM_RO_END;   // == row
            const unsigned b = local / TOPK;
            const unsigned k = (unsigned)idx_s[local];
            out4[V4_MASK + local] = mask[b * Kk + k];
        } else if (g < SM_RB_END) {
            const unsigned local = g - SM_MK_END;
            const unsigned row = local >> 5;
            const unsigned iv  = local & 31u;
            const unsigned b   = row / TOPK;
            const unsigned k   = (unsigned)idx_s[row];
            const int4 v = rb[(b * Kk + k) * 32u + iv];
            out4[V4_RB + local] = make_float4((float)v.x, (float)v.y, (float)v.z, (float)v.w);
        } else if (g < SM_RM_END) {
            const unsigned local = g - SM_RB_END;
            const unsigned row = local >> 5;
            const unsigned iv  = local & 31u;
            const unsigned b   = row / TOPK;
            const unsigned k   = (unsigned)idx_s[row];
            out4[V4_RM + local] = rm[(b * Kk + k) * 32u + iv];
        } else {
            const unsigned local = g - SM_RM_END;
            const unsigned row = local >> 5;
            const unsigned iv  = local & 31u;
            const unsigned b   = row / TOPK;
            const unsigned k   = (unsigned)idx_s[row];
            const int4 v = re[(b * Kk + k) * 32u + iv];
            out4[V4_RE + local] = make_float4((float)v.x, (float)v.y, (float)v.z, (float)v.w);
        }
    }
}

// ---------------------------------------------------------------------------
extern "C" void kernel_launch(void* const* d_in, const int* in_sizes, int n_in,
                              void* d_out, int out_size)
{
    const float* a_s_q   = (const float*)d_in[0];
    const float* a_s_r   = (const float*)d_in[1];
    const float* W       = (const float*)d_in[2];
    const float* s_r     = (const float*)d_in[3];
    const float* h_r     = (const float*)d_in[4];
    const float* r_a     = (const float*)d_in[5];
    const float* r_o     = (const float*)d_in[6];
    const float* mask    = (const float*)d_in[7];
    const int*   rb      = (const int*)d_in[8];
    const float* rm      = (const float*)d_in[9];
    const int*   ratings = (const int*)d_in[10];
    const int*   re      = (const int*)d_in[11];
    float* out = (float*)d_out;

    // opt-in to >48KB dynamic smem (host-side attribute; idempotent,
    // executes at capture time, no device allocation)
    static int attr_done = 0;
    if (!attr_done) {
        cudaFuncSetAttribute(q_kernel,
            cudaFuncAttributeMaxDynamicSharedMemorySize, Q_SMEM);
        cudaFuncSetAttribute(score_topk_kernel,
            cudaFuncAttributeMaxDynamicSharedMemorySize, S_SMEM);
        attr_done = 1;
    }

    q_kernel<<<dim3(Bq, 5), 128, Q_SMEM>>>(a_s_q, W);
    score_topk_kernel<<<Bq, 256, S_SMEM>>>(a_s_r, ratings, out);
    gather_kernel<<<HR_BLOCKS + SM_BLOCKS, 256>>>(
        (const float4*)s_r, (const float4*)h_r, (const float4*)r_a,
        (const float4*)r_o, (const float4*)mask, (const int4*)rb,
        (const float4*)rm, (const int4*)re, (float4*)out);
}